// round 11
// baseline (speedup 1.0000x reference)
#include <cuda_runtime.h>

// LSTM_74122545594502: 3-layer bidirectional LSTM, B=4096 T=256 D=4 H=16.
// Round 11: round-10 design (NB=8 chains/warp, WPC=8, fused gate blocks,
// skewed layers, staggered updates) + PACKED ACTIVATIONS: sigmoid/tanh
// computed on f32x2 pairs (mul2/add2/ffma2 + scalar EX2/RCP), cutting
// activation FMA-pipe ops ~3x. Same numerics as __expf/__fdividef.

namespace {
constexpr int B_ = 4096;
constexpr int T_ = 256;
constexpr int D_ = 4;
constexpr int H_ = 16;
constexpr int NB = 8;                      // chains per warp
constexpr int WPC = 8;                     // warps per CTA
constexpr int NCTA = 2 * (B_ / NB) / WPC;  // 128
constexpr int WPITCH = 36;                 // smem weight row pitch (floats)
}

typedef unsigned long long ull;

__device__ __forceinline__ ull pack2(float x, float y) {
    ull r;
    asm("mov.b64 %0, {%1, %2};" : "=l"(r) : "f"(x), "f"(y));
    return r;
}
__device__ __forceinline__ void unpack2(ull v, float& x, float& y) {
    asm("mov.b64 {%0, %1}, %2;" : "=f"(x), "=f"(y) : "l"(v));
}
__device__ __forceinline__ ull ffma2(ull a, ull b, ull c) {
    ull d;
    asm("fma.rn.f32x2 %0, %1, %2, %3;" : "=l"(d) : "l"(a), "l"(b), "l"(c));
    return d;
}
__device__ __forceinline__ ull mul2(ull a, ull b) {
    ull d;
    asm("mul.rn.f32x2 %0, %1, %2;" : "=l"(d) : "l"(a), "l"(b));
    return d;
}
__device__ __forceinline__ ull add2(ull a, ull b) {
    ull d;
    asm("add.rn.f32x2 %0, %1, %2;" : "=l"(d) : "l"(a), "l"(b));
    return d;
}
__device__ __forceinline__ float ex2f_(float x) {
    float y;
    asm("ex2.approx.f32 %0, %1;" : "=f"(y) : "f"(x));
    return y;
}
__device__ __forceinline__ float rcpf_(float x) {
    float y;
    asm("rcp.approx.f32 %0, %1;" : "=f"(y) : "f"(x));
    return y;
}

// Packed activation constants.
__device__ __forceinline__ ull const2(float v) { return pack2(v, v); }

// sigmoid on both halves: 1/(1+exp(-v)) = 1/(1+2^(v*-log2e))
__device__ __forceinline__ ull sigmoid2(ull v) {
    ull t = mul2(v, const2(-1.4426950408889634f));
    float t0, t1;
    unpack2(t, t0, t1);
    ull s = add2(pack2(ex2f_(t0), ex2f_(t1)), const2(1.0f));
    float s0, s1;
    unpack2(s, s0, s1);
    return pack2(rcpf_(s0), rcpf_(s1));
}
// tanh on both halves: 2*sigmoid(2v)-1, exp via 2^(v*-2log2e)
__device__ __forceinline__ ull tanh2(ull v) {
    ull t = mul2(v, const2(-2.8853900817779268f));
    float t0, t1;
    unpack2(t, t0, t1);
    ull s = add2(pack2(ex2f_(t0), ex2f_(t1)), const2(1.0f));
    float s0, s1;
    unpack2(s, s0, s1);
    ull r = pack2(rcpf_(s0), rcpf_(s1));
    return ffma2(r, const2(2.0f), const2(-1.0f));
}
// tanh if low else sigmoid (per-lane uniform predicate)
__device__ __forceinline__ ull act2_cond(ull v, bool is_tanh) {
    ull t = mul2(v, is_tanh ? const2(-2.8853900817779268f)
                            : const2(-1.4426950408889634f));
    float t0, t1;
    unpack2(t, t0, t1);
    ull s = add2(pack2(ex2f_(t0), ex2f_(t1)), const2(1.0f));
    float s0, s1;
    unpack2(s, s0, s1);
    ull r = pack2(rcpf_(s0), rcpf_(s1));
    return is_tanh ? ffma2(r, const2(2.0f), const2(-1.0f)) : r;
}

struct Params {
    const float* y;
    const float* w[24];  // dir*12 + {Wih1,Whh1,bih1,bhh1, Wih2,...,bhh3}
};

__device__ float g_h3[2][B_][H_];  // final layer-3 h

// 8 FFMA2 for one input index j (8 chains, 2 gate rows); v already loaded.
__device__ __forceinline__ void gstep8v(ull wp0, ull wp1,
                                        ulonglong2 v01, ulonglong2 v23,
                                        ull* A, ull* B) {
    A[0] = ffma2(wp0, v01.x, A[0]);
    A[1] = ffma2(wp0, v01.y, A[1]);
    A[2] = ffma2(wp0, v23.x, A[2]);
    A[3] = ffma2(wp0, v23.y, A[3]);
    B[0] = ffma2(wp1, v01.x, B[0]);
    B[1] = ffma2(wp1, v01.y, B[1]);
    B[2] = ffma2(wp1, v23.x, B[2]);
    B[3] = ffma2(wp1, v23.y, B[3]);
}

// Packed-activation update: activate, bfly(16) exchange, c/h update for
// 8 chains. Low lane ends with chains 0-3 of its unit; high lane 4-7.
__device__ __forceinline__ float4 do_update8(ull* A, ull* B, bool low,
                                             ull& c0, ull& c1, float* hdst) {
#pragma unroll
    for (int k = 0; k < 4; ++k) A[k] = sigmoid2(A[k]);   // i (low) / f (high)
#pragma unroll
    for (int k = 0; k < 4; ++k) B[k] = act2_cond(B[k], low);  // g / o
    ull s0 = low ? A[2] : A[0];
    ull s1 = low ? A[3] : A[1];
    ull s2 = low ? B[2] : B[0];
    ull s3 = low ? B[3] : B[1];
    ull r0 = __shfl_xor_sync(0xffffffffu, s0, 16);
    ull r1 = __shfl_xor_sync(0xffffffffu, s1, 16);
    ull r2 = __shfl_xor_sync(0xffffffffu, s2, 16);
    ull r3 = __shfl_xor_sync(0xffffffffu, s3, 16);
    ull I0 = low ? A[0] : r0, I1 = low ? A[1] : r1;
    ull F0 = low ? r0 : A[2], F1 = low ? r1 : A[3];
    ull G0 = low ? B[0] : r2, G1 = low ? B[1] : r3;
    ull O0 = low ? r2 : B[2], O1 = low ? r3 : B[3];
    c0 = ffma2(F0, c0, mul2(I0, G0));
    c1 = ffma2(F1, c1, mul2(I1, G1));
    ull h01 = mul2(O0, tanh2(c0));
    ull h23 = mul2(O1, tanh2(c1));
    float h0, h1, h2, h3;
    unpack2(h01, h0, h1);
    unpack2(h23, h2, h3);
    float4 h = make_float4(h0, h1, h2, h3);
    *(float4*)hdst = h;
    return h;
}

__global__ void __launch_bounds__(256, 1) lstm_kernel(Params p) {
    __shared__ float wsm[2][64][WPITCH];    // L2/L3 weights [layer][row][ih|hh]
    __shared__ __align__(16) float xs[WPC][2][D_][NB];     // x per warp
    __shared__ __align__(16) float hs[WPC][3][2][H_][NB];  // h per warp/layer

    const int tid  = threadIdx.x;
    const int lane = tid & 31;
    const int w    = tid >> 5;
    const int dir  = blockIdx.x >> 6;               // 64 CTAs per dir
    const int gidx = (blockIdx.x & 63) * WPC + w;   // 0..511 per dir
    const int b0   = gidx * NB;
    const bool low = lane < 16;
    const int unit = lane & 15;

    const float* const* ws = &p.w[dir * 12];

    // ---- cooperative fill of L2/L3 weight table ----
    for (int i = tid; i < 2 * 64 * 32; i += 256) {
        int layer = i >> 11, rem = i & 2047, row = rem >> 5, col = rem & 31;
        float v = (col < 16) ? ws[4 + layer * 4][row * 16 + col]
                             : ws[5 + layer * 4][row * 16 + (col - 16)];
        wsm[layer][row][col] = v;
    }

    // ---- L1 weights pre-packed (duplicated) + per-row biases ----
    const int r0 = lane, r1 = lane + 32;
    ull wxp0[D_], wxp1[D_], whp0[H_], whp1[H_];
#pragma unroll
    for (int j = 0; j < D_; ++j) {
        float a = ws[0][r0 * D_ + j], b = ws[0][r1 * D_ + j];
        wxp0[j] = pack2(a, a);
        wxp1[j] = pack2(b, b);
    }
#pragma unroll
    for (int j = 0; j < H_; ++j) {
        float a = ws[1][r0 * H_ + j], b = ws[1][r1 * H_ + j];
        whp0[j] = pack2(a, a);
        whp1[j] = pack2(b, b);
    }
    const float b1l = ws[2][r0] + ws[3][r0],   b1h = ws[2][r1] + ws[3][r1];
    const float b2l = ws[6][r0] + ws[7][r0],   b2h = ws[6][r1] + ws[7][r1];
    const float b3l = ws[10][r0] + ws[11][r0], b3h = ws[10][r1] + ws[11][r1];
    const ull bp1l = pack2(b1l, b1l), bp1h = pack2(b1h, b1h);
    const ull bp2l = pack2(b2l, b2l), bp2h = pack2(b2h, b2h);
    const ull bp3l = pack2(b3l, b3l), bp3h = pack2(b3h, b3h);

    // ---- init: both h buffers zero; x buffer 0 = x[step 0] ----
    {
        float4* hp = (float4*)&hs[w][0][0][0][0];
#pragma unroll
        for (int i = lane; i < 3 * 2 * H_ * NB / 4; i += 32)
            hp[i] = make_float4(0.f, 0.f, 0.f, 0.f);
    }
    const int xc = lane >> 2, xj = lane & 3;  // chain 0..7, component 0..3
    {
        int tt = dir ? (T_ - 1) : 0;
        xs[w][0][xj][xc] = p.y[((size_t)(b0 + xc) * T_ + tt) * D_ + xj];
    }
    __syncthreads();  // weight table + buffers visible

    ull c1p0 = 0ull, c1p1 = 0ull, c2p0 = 0ull, c2p1 = 0ull, c3p0 = 0ull, c3p1 = 0ull;
    float4 h3f = make_float4(0.f, 0.f, 0.f, 0.f);
    const int hoff = low ? 0 : 4;

    // Iteration K (skewed): gates of L1(step K), L2(K-1), L3(K-2), all read
    // buffer rb=K&1, updates write wb. Fused input loads:
    //  block A: x->L1; h0->L1-hh & L2-ih;  U1
    //  block B: h1->L2-hh & L3-ih;         U2
    //  block C: h2->L3-hh;                 U3
#define ITER(K, U1, U2, U3) do {                                              \
    const int rb_ = (K) & 1, wb_ = rb_ ^ 1;                                   \
    int tt_ = dir ? (T_ - 2 - (K)) : ((K) + 1);                               \
    tt_ = tt_ < 0 ? 0 : (tt_ > T_ - 1 ? T_ - 1 : tt_);                        \
    float xn_ = p.y[((size_t)(b0 + xc) * T_ + tt_) * D_ + xj];                \
    ull A1_[4], B1_[4], A2_[4], B2_[4], A3_[4], B3_[4];                       \
    _Pragma("unroll")                                                         \
    for (int k_ = 0; k_ < 4; ++k_) {                                          \
        A1_[k_] = bp1l; B1_[k_] = bp1h;                                       \
        A2_[k_] = bp2l; B2_[k_] = bp2h;                                       \
    }                                                                         \
    /* block A */                                                             \
    {                                                                         \
        const ulonglong2* xv = (const ulonglong2*)&xs[w][rb_][0][0];          \
        _Pragma("unroll")                                                     \
        for (int j_ = 0; j_ < D_; ++j_)                                       \
            gstep8v(wxp0[j_], wxp1[j_], xv[2 * j_], xv[2 * j_ + 1], A1_, B1_);\
        const ulonglong2* h0v = (const ulonglong2*)&hs[w][0][rb_][0][0];      \
        _Pragma("unroll")                                                     \
        for (int jq_ = 0; jq_ < 4; ++jq_) {                                   \
            float4 w20 = *(const float4*)&wsm[0][r0][4 * jq_];                \
            float4 w21 = *(const float4*)&wsm[0][r1][4 * jq_];                \
            _Pragma("unroll")                                                 \
            for (int jj_ = 0; jj_ < 4; ++jj_) {                               \
                int j_ = 4 * jq_ + jj_;                                       \
                ulonglong2 v01 = h0v[2 * j_], v23 = h0v[2 * j_ + 1];          \
                gstep8v(whp0[j_], whp1[j_], v01, v23, A1_, B1_);              \
                float s0 = ((const float*)&w20)[jj_];                         \
                float s1 = ((const float*)&w21)[jj_];                         \
                gstep8v(pack2(s0, s0), pack2(s1, s1), v01, v23, A2_, B2_);    \
            }                                                                 \
        }                                                                     \
    }                                                                         \
    if (U1) do_update8(A1_, B1_, low, c1p0, c1p1,                             \
                       &hs[w][0][wb_][unit][0] + hoff);                       \
    /* block B */                                                             \
    _Pragma("unroll")                                                         \
    for (int k_ = 0; k_ < 4; ++k_) { A3_[k_] = bp3l; B3_[k_] = bp3h; }        \
    {                                                                         \
        const ulonglong2* h1v = (const ulonglong2*)&hs[w][1][rb_][0][0];      \
        _Pragma("unroll")                                                     \
        for (int jq_ = 0; jq_ < 4; ++jq_) {                                   \
            float4 w2h0 = *(const float4*)&wsm[0][r0][16 + 4 * jq_];          \
            float4 w2h1 = *(const float4*)&wsm[0][r1][16 + 4 * jq_];          \
            float4 w3i0 = *(const float4*)&wsm[1][r0][4 * jq_];               \
            float4 w3i1 = *(const float4*)&wsm[1][r1][4 * jq_];               \
            _Pragma("unroll")                                                 \
            for (int jj_ = 0; jj_ < 4; ++jj_) {                               \
                int j_ = 4 * jq_ + jj_;                                       \
                ulonglong2 v01 = h1v[2 * j_], v23 = h1v[2 * j_ + 1];          \
                float s0 = ((const float*)&w2h0)[jj_];                        \
                float s1 = ((const float*)&w2h1)[jj_];                        \
                gstep8v(pack2(s0, s0), pack2(s1, s1), v01, v23, A2_, B2_);    \
                float t0 = ((const float*)&w3i0)[jj_];                        \
                float t1 = ((const float*)&w3i1)[jj_];                        \
                gstep8v(pack2(t0, t0), pack2(t1, t1), v01, v23, A3_, B3_);    \
            }                                                                 \
        }                                                                     \
    }                                                                         \
    if (U2) do_update8(A2_, B2_, low, c2p0, c2p1,                             \
                       &hs[w][1][wb_][unit][0] + hoff);                       \
    /* block C */                                                             \
    {                                                                         \
        const ulonglong2* h2v = (const ulonglong2*)&hs[w][2][rb_][0][0];      \
        _Pragma("unroll")                                                     \
        for (int jq_ = 0; jq_ < 4; ++jq_) {                                   \
            float4 w3h0 = *(const float4*)&wsm[1][r0][16 + 4 * jq_];          \
            float4 w3h1 = *(const float4*)&wsm[1][r1][16 + 4 * jq_];          \
            _Pragma("unroll")                                                 \
            for (int jj_ = 0; jj_ < 4; ++jj_) {                               \
                int j_ = 4 * jq_ + jj_;                                       \
                float s0 = ((const float*)&w3h0)[jj_];                        \
                float s1 = ((const float*)&w3h1)[jj_];                        \
                gstep8v(pack2(s0, s0), pack2(s1, s1),                         \
                        h2v[2 * j_], h2v[2 * j_ + 1], A3_, B3_);              \
            }                                                                 \
        }                                                                     \
    }                                                                         \
    if (U3) h3f = do_update8(A3_, B3_, low, c3p0, c3p1,                       \
                             &hs[w][2][wb_][unit][0] + hoff);                 \
    xs[w][wb_][xj][xc] = xn_;                                                 \
    __syncwarp();                                                             \
} while (0)

    ITER(0, true, false, false);
    ITER(1, true, true, false);
#pragma unroll 1
    for (int k = 2; k < T_; ++k) ITER(k, true, true, true);
    ITER(T_, false, true, true);
    ITER(T_ + 1, false, false, true);
#undef ITER

    // final layer-3 h (step T-1): low lane -> chains 0-3; high -> 4-7.
    {
        int cb = b0 + (low ? 0 : 4);
        g_h3[dir][cb + 0][unit] = h3f.x;
        g_h3[dir][cb + 1][unit] = h3f.y;
        g_h3[dir][cb + 2][unit] = h3f.z;
        g_h3[dir][cb + 3][unit] = h3f.w;
    }
}

// out[b,k] = b_out[k] + sum_j W_out[k][j]*hf3[b][j] + W_out[k][16+j]*hb3[b][j]
__global__ void proj_kernel(const float* __restrict__ Wo,
                            const float* __restrict__ bo,
                            float* __restrict__ out) {
    int b = blockIdx.x * blockDim.x + threadIdx.x;
    if (b >= B_) return;
    float a0 = bo[0], a1 = bo[1], a2 = bo[2], a3 = bo[3];
#pragma unroll
    for (int j = 0; j < H_; ++j) {
        float hf = g_h3[0][b][j];
        a0 += Wo[0 * 32 + j] * hf;
        a1 += Wo[1 * 32 + j] * hf;
        a2 += Wo[2 * 32 + j] * hf;
        a3 += Wo[3 * 32 + j] * hf;
    }
#pragma unroll
    for (int j = 0; j < H_; ++j) {
        float hb = g_h3[1][b][j];
        a0 += Wo[0 * 32 + 16 + j] * hb;
        a1 += Wo[1 * 32 + 16 + j] * hb;
        a2 += Wo[2 * 32 + 16 + j] * hb;
        a3 += Wo[3 * 32 + 16 + j] * hb;
    }
    ((float4*)out)[b] = make_float4(a0, a1, a2, a3);
}

extern "C" void kernel_launch(void* const* d_in, const int* in_sizes, int n_in,
                              void* d_out, int out_size) {
    (void)in_sizes; (void)n_in; (void)out_size;
    Params p;
    p.y = (const float*)d_in[0];
    for (int i = 0; i < 24; ++i) p.w[i] = (const float*)d_in[1 + i];

    lstm_kernel<<<NCTA, 256>>>(p);
    proj_kernel<<<(B_ + 127) / 128, 128>>>((const float*)d_in[25],
                                           (const float*)d_in[26],
                                           (float*)d_out);
}

// round 12
// speedup vs baseline: 1.3560x; 1.3560x over previous
#include <cuda_runtime.h>

// LSTM_74122545594502: 3-layer bidirectional LSTM, B=4096 T=256 D=4 H=16.
// Round 12: round-10 design (NB=8 chains/warp, WPC=8, fused gate blocks,
// skewed layers, staggered updates, scalar activations) with HW tanh:
//   tanh(x)    -> MUFU.TANH (1 op)
//   sigmoid(x) -> 0.5*tanh(x/2)+0.5, with the x/2 PRE-SCALED into the
//                 weights/biases of sigmoid gate rows (i,f,o) at load time.
// Activation cost drops 120 MUFU + ~240 FMA -> 60 MUFU + ~60 FMA per
// warp-step. Error budget: MUFU.TANH ~1e-4 worst case vs 1e-3 threshold.

namespace {
constexpr int B_ = 4096;
constexpr int T_ = 256;
constexpr int D_ = 4;
constexpr int H_ = 16;
constexpr int NB = 8;                      // chains per warp
constexpr int WPC = 8;                     // warps per CTA
constexpr int NCTA = 2 * (B_ / NB) / WPC;  // 128
constexpr int WPITCH = 36;                 // smem weight row pitch (floats)
}

typedef unsigned long long ull;

__device__ __forceinline__ ull pack2(float x, float y) {
    ull r;
    asm("mov.b64 %0, {%1, %2};" : "=l"(r) : "f"(x), "f"(y));
    return r;
}
__device__ __forceinline__ void unpack2(ull v, float& x, float& y) {
    asm("mov.b64 {%0, %1}, %2;" : "=f"(x), "=f"(y) : "l"(v));
}
__device__ __forceinline__ ull ffma2(ull a, ull b, ull c) {
    ull d;
    asm("fma.rn.f32x2 %0, %1, %2, %3;" : "=l"(d) : "l"(a), "l"(b), "l"(c));
    return d;
}
__device__ __forceinline__ ull mul2(ull a, ull b) {
    ull d;
    asm("mul.rn.f32x2 %0, %1, %2;" : "=l"(d) : "l"(a), "l"(b));
    return d;
}

// HW tanh (MUFU.TANH).
__device__ __forceinline__ float tanhap(float x) {
    float y;
    asm("tanh.approx.f32 %0, %1;" : "=f"(y) : "f"(x));
    return y;
}
// sigmoid from PRE-SCALED input (x already = 0.5 * preactivation).
__device__ __forceinline__ float sigp(float x) {
    return fmaf(tanhap(x), 0.5f, 0.5f);
}

struct Params {
    const float* y;
    const float* w[24];  // dir*12 + {Wih1,Whh1,bih1,bhh1, Wih2,...,bhh3}
};

__device__ float g_h3[2][B_][H_];  // final layer-3 h

// 8 FFMA2 for one input index j (8 chains, 2 gate rows); v already loaded.
__device__ __forceinline__ void gstep8v(ull wp0, ull wp1,
                                        ulonglong2 v01, ulonglong2 v23,
                                        ull* A, ull* B) {
    A[0] = ffma2(wp0, v01.x, A[0]);
    A[1] = ffma2(wp0, v01.y, A[1]);
    A[2] = ffma2(wp0, v23.x, A[2]);
    A[3] = ffma2(wp0, v23.y, A[3]);
    B[0] = ffma2(wp1, v01.x, B[0]);
    B[1] = ffma2(wp1, v01.y, B[1]);
    B[2] = ffma2(wp1, v23.x, B[2]);
    B[3] = ffma2(wp1, v23.y, B[3]);
}

// Activate + bfly(16) exchange + c/h update for 8 chains.
// A rows (i low / f high): sigmoid, inputs pre-scaled by 0.5.
// B rows: g (tanh, low lanes, unscaled) / o (sigmoid, high lanes, pre-scaled).
__device__ __forceinline__ float4 do_update8(ull* A, ull* B, bool low,
                                             ull& c0, ull& c1, float* hdst) {
    float af[8], bf[8];
#pragma unroll
    for (int k = 0; k < 4; ++k) {
        unpack2(A[k], af[2 * k], af[2 * k + 1]);
        unpack2(B[k], bf[2 * k], bf[2 * k + 1]);
    }
#pragma unroll
    for (int i = 0; i < 8; ++i) {
        af[i] = sigp(af[i]);
        bf[i] = low ? tanhap(bf[i]) : sigp(bf[i]);
    }
#pragma unroll
    for (int k = 0; k < 4; ++k) {
        A[k] = pack2(af[2 * k], af[2 * k + 1]);
        B[k] = pack2(bf[2 * k], bf[2 * k + 1]);
    }
    ull s0 = low ? A[2] : A[0];
    ull s1 = low ? A[3] : A[1];
    ull s2 = low ? B[2] : B[0];
    ull s3 = low ? B[3] : B[1];
    ull r0 = __shfl_xor_sync(0xffffffffu, s0, 16);
    ull r1 = __shfl_xor_sync(0xffffffffu, s1, 16);
    ull r2 = __shfl_xor_sync(0xffffffffu, s2, 16);
    ull r3 = __shfl_xor_sync(0xffffffffu, s3, 16);
    ull I0 = low ? A[0] : r0, I1 = low ? A[1] : r1;
    ull F0 = low ? r0 : A[2], F1 = low ? r1 : A[3];
    ull G0 = low ? B[0] : r2, G1 = low ? B[1] : r3;
    ull O0 = low ? r2 : B[2], O1 = low ? r3 : B[3];
    c0 = ffma2(F0, c0, mul2(I0, G0));
    c1 = ffma2(F1, c1, mul2(I1, G1));
    float ca0, ca1, ca2, ca3, o0, o1, o2, o3;
    unpack2(c0, ca0, ca1);
    unpack2(c1, ca2, ca3);
    unpack2(O0, o0, o1);
    unpack2(O1, o2, o3);
    float4 h = make_float4(o0 * tanhap(ca0), o1 * tanhap(ca1),
                           o2 * tanhap(ca2), o3 * tanhap(ca3));
    *(float4*)hdst = h;
    return h;
}

__global__ void __launch_bounds__(256, 1) lstm_kernel(Params p) {
    __shared__ float wsm[2][64][WPITCH];    // L2/L3 weights [layer][row][ih|hh]
    __shared__ __align__(16) float xs[WPC][2][D_][NB];     // x per warp
    __shared__ __align__(16) float hs[WPC][3][2][H_][NB];  // h per warp/layer

    const int tid  = threadIdx.x;
    const int lane = tid & 31;
    const int w    = tid >> 5;
    const int dir  = blockIdx.x >> 6;               // 64 CTAs per dir
    const int gidx = (blockIdx.x & 63) * WPC + w;   // 0..511 per dir
    const int b0   = gidx * NB;
    const bool low = lane < 16;
    const int unit = lane & 15;

    const float* const* ws = &p.w[dir * 12];

    // ---- cooperative fill of L2/L3 weight table ----
    // Sigmoid gate rows (i: 0-15, f: 16-31, o: 48-63) pre-scaled by 0.5;
    // tanh rows (g: 32-47) unscaled.
    for (int i = tid; i < 2 * 64 * 32; i += 256) {
        int layer = i >> 11, rem = i & 2047, row = rem >> 5, col = rem & 31;
        float v = (col < 16) ? ws[4 + layer * 4][row * 16 + col]
                             : ws[5 + layer * 4][row * 16 + (col - 16)];
        float sc = (row >= 32 && row < 48) ? 1.0f : 0.5f;
        wsm[layer][row][col] = v * sc;
    }

    // ---- L1 weights pre-packed (duplicated), pre-scaled; per-row biases ----
    const int r0 = lane, r1 = lane + 32;
    const float sc0 = 0.5f;                     // r0 rows (i/f): sigmoid
    const float sc1 = low ? 1.0f : 0.5f;        // r1: g (tanh) low, o high
    ull wxp0[D_], wxp1[D_], whp0[H_], whp1[H_];
#pragma unroll
    for (int j = 0; j < D_; ++j) {
        float a = ws[0][r0 * D_ + j] * sc0, b = ws[0][r1 * D_ + j] * sc1;
        wxp0[j] = pack2(a, a);
        wxp1[j] = pack2(b, b);
    }
#pragma unroll
    for (int j = 0; j < H_; ++j) {
        float a = ws[1][r0 * H_ + j] * sc0, b = ws[1][r1 * H_ + j] * sc1;
        whp0[j] = pack2(a, a);
        whp1[j] = pack2(b, b);
    }
    const float b1l = (ws[2][r0] + ws[3][r0]) * sc0,   b1h = (ws[2][r1] + ws[3][r1]) * sc1;
    const float b2l = (ws[6][r0] + ws[7][r0]) * sc0,   b2h = (ws[6][r1] + ws[7][r1]) * sc1;
    const float b3l = (ws[10][r0] + ws[11][r0]) * sc0, b3h = (ws[10][r1] + ws[11][r1]) * sc1;
    const ull bp1l = pack2(b1l, b1l), bp1h = pack2(b1h, b1h);
    const ull bp2l = pack2(b2l, b2l), bp2h = pack2(b2h, b2h);
    const ull bp3l = pack2(b3l, b3l), bp3h = pack2(b3h, b3h);

    // ---- init: both h buffers zero; x buffer 0 = x[step 0] ----
    {
        float4* hp = (float4*)&hs[w][0][0][0][0];
#pragma unroll
        for (int i = lane; i < 3 * 2 * H_ * NB / 4; i += 32)
            hp[i] = make_float4(0.f, 0.f, 0.f, 0.f);
    }
    const int xc = lane >> 2, xj = lane & 3;  // chain 0..7, component 0..3
    {
        int tt = dir ? (T_ - 1) : 0;
        xs[w][0][xj][xc] = p.y[((size_t)(b0 + xc) * T_ + tt) * D_ + xj];
    }
    __syncthreads();  // weight table + buffers visible

    ull c1p0 = 0ull, c1p1 = 0ull, c2p0 = 0ull, c2p1 = 0ull, c3p0 = 0ull, c3p1 = 0ull;
    float4 h3f = make_float4(0.f, 0.f, 0.f, 0.f);
    const int hoff = low ? 0 : 4;

    // Iteration K (skewed): gates of L1(step K), L2(K-1), L3(K-2), all read
    // buffer rb=K&1, updates write wb. Fused input loads:
    //  block A: x->L1; h0->L1-hh & L2-ih;  U1
    //  block B: h1->L2-hh & L3-ih;         U2
    //  block C: h2->L3-hh;                 U3
#define ITER(K, U1, U2, U3) do {                                              \
    const int rb_ = (K) & 1, wb_ = rb_ ^ 1;                                   \
    int tt_ = dir ? (T_ - 2 - (K)) : ((K) + 1);                               \
    tt_ = tt_ < 0 ? 0 : (tt_ > T_ - 1 ? T_ - 1 : tt_);                        \
    float xn_ = p.y[((size_t)(b0 + xc) * T_ + tt_) * D_ + xj];                \
    ull A1_[4], B1_[4], A2_[4], B2_[4], A3_[4], B3_[4];                       \
    _Pragma("unroll")                                                         \
    for (int k_ = 0; k_ < 4; ++k_) {                                          \
        A1_[k_] = bp1l; B1_[k_] = bp1h;                                       \
        A2_[k_] = bp2l; B2_[k_] = bp2h;                                       \
    }                                                                         \
    /* block A */                                                             \
    {                                                                         \
        const ulonglong2* xv = (const ulonglong2*)&xs[w][rb_][0][0];          \
        _Pragma("unroll")                                                     \
        for (int j_ = 0; j_ < D_; ++j_)                                       \
            gstep8v(wxp0[j_], wxp1[j_], xv[2 * j_], xv[2 * j_ + 1], A1_, B1_);\
        const ulonglong2* h0v = (const ulonglong2*)&hs[w][0][rb_][0][0];      \
        _Pragma("unroll")                                                     \
        for (int jq_ = 0; jq_ < 4; ++jq_) {                                   \
            float4 w20 = *(const float4*)&wsm[0][r0][4 * jq_];                \
            float4 w21 = *(const float4*)&wsm[0][r1][4 * jq_];                \
            _Pragma("unroll")                                                 \
            for (int jj_ = 0; jj_ < 4; ++jj_) {                               \
                int j_ = 4 * jq_ + jj_;                                       \
                ulonglong2 v01 = h0v[2 * j_], v23 = h0v[2 * j_ + 1];          \
                gstep8v(whp0[j_], whp1[j_], v01, v23, A1_, B1_);              \
                float s0 = ((const float*)&w20)[jj_];                         \
                float s1 = ((const float*)&w21)[jj_];                         \
                gstep8v(pack2(s0, s0), pack2(s1, s1), v01, v23, A2_, B2_);    \
            }                                                                 \
        }                                                                     \
    }                                                                         \
    if (U1) do_update8(A1_, B1_, low, c1p0, c1p1,                             \
                       &hs[w][0][wb_][unit][0] + hoff);                       \
    /* block B */                                                             \
    _Pragma("unroll")                                                         \
    for (int k_ = 0; k_ < 4; ++k_) { A3_[k_] = bp3l; B3_[k_] = bp3h; }        \
    {                                                                         \
        const ulonglong2* h1v = (const ulonglong2*)&hs[w][1][rb_][0][0];      \
        _Pragma("unroll")                                                     \
        for (int jq_ = 0; jq_ < 4; ++jq_) {                                   \
            float4 w2h0 = *(const float4*)&wsm[0][r0][16 + 4 * jq_];          \
            float4 w2h1 = *(const float4*)&wsm[0][r1][16 + 4 * jq_];          \
            float4 w3i0 = *(const float4*)&wsm[1][r0][4 * jq_];               \
            float4 w3i1 = *(const float4*)&wsm[1][r1][4 * jq_];               \
            _Pragma("unroll")                                                 \
            for (int jj_ = 0; jj_ < 4; ++jj_) {                               \
                int j_ = 4 * jq_ + jj_;                                       \
                ulonglong2 v01 = h1v[2 * j_], v23 = h1v[2 * j_ + 1];          \
                float s0 = ((const float*)&w2h0)[jj_];                        \
                float s1 = ((const float*)&w2h1)[jj_];                        \
                gstep8v(pack2(s0, s0), pack2(s1, s1), v01, v23, A2_, B2_);    \
                float t0 = ((const float*)&w3i0)[jj_];                        \
                float t1 = ((const float*)&w3i1)[jj_];                        \
                gstep8v(pack2(t0, t0), pack2(t1, t1), v01, v23, A3_, B3_);    \
            }                                                                 \
        }                                                                     \
    }                                                                         \
    if (U2) do_update8(A2_, B2_, low, c2p0, c2p1,                             \
                       &hs[w][1][wb_][unit][0] + hoff);                       \
    /* block C */                                                             \
    {                                                                         \
        const ulonglong2* h2v = (const ulonglong2*)&hs[w][2][rb_][0][0];      \
        _Pragma("unroll")                                                     \
        for (int jq_ = 0; jq_ < 4; ++jq_) {                                   \
            float4 w3h0 = *(const float4*)&wsm[1][r0][16 + 4 * jq_];          \
            float4 w3h1 = *(const float4*)&wsm[1][r1][16 + 4 * jq_];          \
            _Pragma("unroll")                                                 \
            for (int jj_ = 0; jj_ < 4; ++jj_) {                               \
                int j_ = 4 * jq_ + jj_;                                       \
                float s0 = ((const float*)&w3h0)[jj_];                        \
                float s1 = ((const float*)&w3h1)[jj_];                        \
                gstep8v(pack2(s0, s0), pack2(s1, s1),                         \
                        h2v[2 * j_], h2v[2 * j_ + 1], A3_, B3_);              \
            }                                                                 \
        }                                                                     \
    }                                                                         \
    if (U3) h3f = do_update8(A3_, B3_, low, c3p0, c3p1,                       \
                             &hs[w][2][wb_][unit][0] + hoff);                 \
    xs[w][wb_][xj][xc] = xn_;                                                 \
    __syncwarp();                                                             \
} while (0)

    ITER(0, true, false, false);
    ITER(1, true, true, false);
#pragma unroll 1
    for (int k = 2; k < T_; ++k) ITER(k, true, true, true);
    ITER(T_, false, true, true);
    ITER(T_ + 1, false, false, true);
#undef ITER

    // final layer-3 h (step T-1): low lane -> chains 0-3; high -> 4-7.
    {
        int cb = b0 + (low ? 0 : 4);
        g_h3[dir][cb + 0][unit] = h3f.x;
        g_h3[dir][cb + 1][unit] = h3f.y;
        g_h3[dir][cb + 2][unit] = h3f.z;
        g_h3[dir][cb + 3][unit] = h3f.w;
    }
}

// out[b,k] = b_out[k] + sum_j W_out[k][j]*hf3[b][j] + W_out[k][16+j]*hb3[b][j]
__global__ void proj_kernel(const float* __restrict__ Wo,
                            const float* __restrict__ bo,
                            float* __restrict__ out) {
    int b = blockIdx.x * blockDim.x + threadIdx.x;
    if (b >= B_) return;
    float a0 = bo[0], a1 = bo[1], a2 = bo[2], a3 = bo[3];
#pragma unroll
    for (int j = 0; j < H_; ++j) {
        float hf = g_h3[0][b][j];
        a0 += Wo[0 * 32 + j] * hf;
        a1 += Wo[1 * 32 + j] * hf;
        a2 += Wo[2 * 32 + j] * hf;
        a3 += Wo[3 * 32 + j] * hf;
    }
#pragma unroll
    for (int j = 0; j < H_; ++j) {
        float hb = g_h3[1][b][j];
        a0 += Wo[0 * 32 + 16 + j] * hb;
        a1 += Wo[1 * 32 + 16 + j] * hb;
        a2 += Wo[2 * 32 + 16 + j] * hb;
        a3 += Wo[3 * 32 + 16 + j] * hb;
    }
    ((float4*)out)[b] = make_float4(a0, a1, a2, a3);
}

extern "C" void kernel_launch(void* const* d_in, const int* in_sizes, int n_in,
                              void* d_out, int out_size) {
    (void)in_sizes; (void)n_in; (void)out_size;
    Params p;
    p.y = (const float*)d_in[0];
    for (int i = 0; i < 24; ++i) p.w[i] = (const float*)d_in[1 + i];

    lstm_kernel<<<NCTA, 256>>>(p);
    proj_kernel<<<(B_ + 127) / 128, 128>>>((const float*)d_in[25],
                                           (const float*)d_in[26],
                                           (float*)d_out);
}

// round 13
// speedup vs baseline: 1.4677x; 1.0824x over previous
#include <cuda_runtime.h>

// LSTM_74122545594502: 3-layer bidirectional LSTM, B=4096 T=256 D=4 H=16.
// Round 13: round-12 design (skewed layers, fused gate blocks, staggered
// updates, MUFU.TANH activations with pre-scaled sigmoid weights) with
// MIXED-NB WARPS to fill all 148 SMs:
//   grid = 148 CTAs x 256 thr (74 CTAs/dir, 56 chains each; 48 ghost/dir
//   clamped on load, store-suppressed). Warps 0-3: NB=8; warps 4-7: NB=6.
//   Every SMSP hosts one NB8 + one NB6 warp -> per-SMSP FFMA2 load drops
//   12.5% vs round 12 AND no SM idles.

namespace {
constexpr int B_ = 4096;
constexpr int T_ = 256;
constexpr int D_ = 4;
constexpr int H_ = 16;
constexpr int WPC = 8;
constexpr int CTAS_PER_DIR = 74;
constexpr int NCTA = 2 * CTAS_PER_DIR;    // 148
constexpr int CHAINS_PER_CTA = 56;        // 4*8 + 4*6
constexpr int WPITCH = 36;                // smem weight row pitch (floats)
}

typedef unsigned long long ull;

__device__ __forceinline__ ull pack2(float x, float y) {
    ull r;
    asm("mov.b64 %0, {%1, %2};" : "=l"(r) : "f"(x), "f"(y));
    return r;
}
__device__ __forceinline__ void unpack2(ull v, float& x, float& y) {
    asm("mov.b64 {%0, %1}, %2;" : "=f"(x), "=f"(y) : "l"(v));
}
__device__ __forceinline__ ull ffma2(ull a, ull b, ull c) {
    ull d;
    asm("fma.rn.f32x2 %0, %1, %2, %3;" : "=l"(d) : "l"(a), "l"(b), "l"(c));
    return d;
}
__device__ __forceinline__ ull mul2(ull a, ull b) {
    ull d;
    asm("mul.rn.f32x2 %0, %1, %2;" : "=l"(d) : "l"(a), "l"(b));
    return d;
}
__device__ __forceinline__ float tanhap(float x) {
    float y;
    asm("tanh.approx.f32 %0, %1;" : "=f"(y) : "f"(x));
    return y;
}
// sigmoid from PRE-SCALED input (x already = 0.5 * preactivation).
__device__ __forceinline__ float sigp(float x) {
    return fmaf(tanhap(x), 0.5f, 0.5f);
}

struct Params {
    const float* y;
    const float* w[24];  // dir*12 + {Wih1,Whh1,bih1,bhh1, Wih2,...,bhh3}
};

__device__ float g_h3[2][B_][H_];  // final layer-3 h

// Load NP f32x2 chain-pairs for one input index j (row of 8 floats).
template <int NP>
__device__ __forceinline__ void loadv(const float* vj, ull* v) {
    ulonglong2 a = *(const ulonglong2*)vj;
    v[0] = a.x; v[1] = a.y;
    if (NP == 4) {
        ulonglong2 b = *(const ulonglong2*)(vj + 4);
        v[2] = b.x; v[3] = b.y;
    } else {
        v[2] = *(const ull*)(vj + 4);
    }
}

template <int NP>
__device__ __forceinline__ void gsteps(ull wp0, ull wp1, const ull* v,
                                       ull* A, ull* B) {
#pragma unroll
    for (int k = 0; k < NP; ++k) {
        A[k] = ffma2(wp0, v[k], A[k]);
        B[k] = ffma2(wp1, v[k], B[k]);
    }
}

// Activate + bfly(16) exchange + c/h update.
// A rows (i low / f high): sigmoid (pre-scaled). B rows: g(tanh, low) /
// o(sigmoid pre-scaled, high). Returns this lane's h chain values.
template <int NP>
__device__ __forceinline__ float4 do_update(ull* A, ull* B, bool low,
                                            ull& c0, ull& c1, float* hrow);

template <>
__device__ __forceinline__ float4 do_update<4>(ull* A, ull* B, bool low,
                                               ull& c0, ull& c1, float* hrow) {
    float af[8], bf[8];
#pragma unroll
    for (int k = 0; k < 4; ++k) {
        unpack2(A[k], af[2 * k], af[2 * k + 1]);
        unpack2(B[k], bf[2 * k], bf[2 * k + 1]);
    }
#pragma unroll
    for (int i = 0; i < 8; ++i) {
        af[i] = sigp(af[i]);
        bf[i] = low ? tanhap(bf[i]) : sigp(bf[i]);
    }
#pragma unroll
    for (int k = 0; k < 4; ++k) {
        A[k] = pack2(af[2 * k], af[2 * k + 1]);
        B[k] = pack2(bf[2 * k], bf[2 * k + 1]);
    }
    ull s0 = low ? A[2] : A[0];
    ull s1 = low ? A[3] : A[1];
    ull s2 = low ? B[2] : B[0];
    ull s3 = low ? B[3] : B[1];
    ull r0 = __shfl_xor_sync(0xffffffffu, s0, 16);
    ull r1 = __shfl_xor_sync(0xffffffffu, s1, 16);
    ull r2 = __shfl_xor_sync(0xffffffffu, s2, 16);
    ull r3 = __shfl_xor_sync(0xffffffffu, s3, 16);
    ull I0 = low ? A[0] : r0, I1 = low ? A[1] : r1;
    ull F0 = low ? r0 : A[2], F1 = low ? r1 : A[3];
    ull G0 = low ? B[0] : r2, G1 = low ? B[1] : r3;
    ull O0 = low ? r2 : B[2], O1 = low ? r3 : B[3];
    c0 = ffma2(F0, c0, mul2(I0, G0));
    c1 = ffma2(F1, c1, mul2(I1, G1));
    float ca0, ca1, ca2, ca3, o0, o1, o2, o3;
    unpack2(c0, ca0, ca1);
    unpack2(c1, ca2, ca3);
    unpack2(O0, o0, o1);
    unpack2(O1, o2, o3);
    float4 h = make_float4(o0 * tanhap(ca0), o1 * tanhap(ca1),
                           o2 * tanhap(ca2), o3 * tanhap(ca3));
    *(float4*)(hrow + (low ? 0 : 4)) = h;
    return h;
}

template <>
__device__ __forceinline__ float4 do_update<3>(ull* A, ull* B, bool low,
                                               ull& c0, ull& c1, float* hrow) {
    float af[6], bf[6];
#pragma unroll
    for (int k = 0; k < 3; ++k) {
        unpack2(A[k], af[2 * k], af[2 * k + 1]);
        unpack2(B[k], bf[2 * k], bf[2 * k + 1]);
    }
#pragma unroll
    for (int i = 0; i < 6; ++i) {
        af[i] = sigp(af[i]);
        bf[i] = low ? tanhap(bf[i]) : sigp(bf[i]);
    }
#pragma unroll
    for (int k = 0; k < 3; ++k) {
        A[k] = pack2(af[2 * k], af[2 * k + 1]);
        B[k] = pack2(bf[2 * k], bf[2 * k + 1]);
    }
    // low keeps pair 0 (chains 0,1); high keeps pairs 1,2 (chains 2-5).
    // shfl payloads: low sends A1/A2/B1/B2 up; high sends A0/B0 down.
    ull rA1 = __shfl_xor_sync(0xffffffffu, low ? A[1] : A[0], 16);
    ull rA2 = __shfl_xor_sync(0xffffffffu, low ? A[2] : A[0], 16);
    ull rB1 = __shfl_xor_sync(0xffffffffu, low ? B[1] : B[0], 16);
    ull rB2 = __shfl_xor_sync(0xffffffffu, low ? B[2] : B[0], 16);
    float4 h;
    if (low) {
        // pair 0: I=A0(own i), F=partner A0 (rA1), G=B0, O=partner B0 (rB1)
        c0 = ffma2(rA1, c0, mul2(A[0], B[0]));
        float ca, cb, o0, o1;
        unpack2(c0, ca, cb);
        unpack2(rB1, o0, o1);
        h = make_float4(o0 * tanhap(ca), o1 * tanhap(cb), 0.f, 0.f);
        *(ull*)(hrow + 0) = pack2(h.x, h.y);
    } else {
        // pairs 1,2: I=partner A1/A2 (rA1,rA2), F=own A1/A2, G=partner B1/B2,
        // O=own B1/B2
        c0 = ffma2(A[1], c0, mul2(rA1, rB1));
        c1 = ffma2(A[2], c1, mul2(rA2, rB2));
        float ca0, ca1, ca2, ca3, o0, o1, o2, o3;
        unpack2(c0, ca0, ca1);
        unpack2(c1, ca2, ca3);
        unpack2(B[1], o0, o1);
        unpack2(B[2], o2, o3);
        h = make_float4(o0 * tanhap(ca0), o1 * tanhap(ca1),
                        o2 * tanhap(ca2), o3 * tanhap(ca3));
        *(ull*)(hrow + 2) = pack2(h.x, h.y);
        *(ull*)(hrow + 4) = pack2(h.z, h.w);
    }
    return h;
}

// Per-warp LSTM driver. NP = chain pairs (4 -> NB=8, 3 -> NB=6).
template <int NP>
__device__ __forceinline__ void run_warp(
    const float* __restrict__ y,
    float (*xsw)[D_][8],           // [buf][j][c]
    float (*hsw)[2][H_][8],        // [layer][buf][j][c]
    const float (*wsm)[64][WPITCH],
    const ull* wxp0, const ull* wxp1, const ull* whp0, const ull* whp1,
    ull bp1l, ull bp1h, ull bp2l, ull bp2h, ull bp3l, ull bp3h,
    int r0, int r1, bool low, int unit, int lane, int b0, int dir,
    float* g3)                      // &g_h3[dir][0][0]
{
    // init h buffers to zero (this warp's region only)
    {
        float4* hp = (float4*)&hsw[0][0][0][0];
#pragma unroll
        for (int i = lane; i < 3 * 2 * H_ * 8 / 4; i += 32)
            hp[i] = make_float4(0.f, 0.f, 0.f, 0.f);
    }
    // x prefetch mapping: lane -> (chain, component); clamp ghosts.
    const int xc = lane >> 2, xj = lane & 3;
    const int cload = xc < 2 * NP ? xc : 2 * NP - 1;
    int bb = b0 + cload;
    if (bb > B_ - 1) bb = B_ - 1;
    const float* ybase = y + (size_t)bb * T_ * D_ + xj;
    {
        int tt = dir ? (T_ - 1) : 0;
        xsw[0][xj][xc] = ybase[tt * D_];
    }
    __syncwarp();

    ull c1p0 = 0ull, c1p1 = 0ull, c2p0 = 0ull, c2p1 = 0ull,
        c3p0 = 0ull, c3p1 = 0ull;
    float4 h3f = make_float4(0.f, 0.f, 0.f, 0.f);

    // Iteration K (skewed): gates of L1(step K), L2(K-1), L3(K-2); reads
    // buffer rb=K&1, updates write wb. Fused input loads:
    //  block A: x->L1; h0->L1-hh & L2-ih;  U1
    //  block B: h1->L2-hh & L3-ih;         U2
    //  block C: h2->L3-hh;                 U3
#define ITER(K, U1, U2, U3) do {                                              \
    const int rb_ = (K) & 1, wb_ = rb_ ^ 1;                                   \
    int tt_ = dir ? (T_ - 2 - (K)) : ((K) + 1);                               \
    tt_ = tt_ < 0 ? 0 : (tt_ > T_ - 1 ? T_ - 1 : tt_);                        \
    float xn_ = ybase[tt_ * D_];                                              \
    ull A1_[NP], B1_[NP], A2_[NP], B2_[NP], A3_[NP], B3_[NP];                 \
    _Pragma("unroll")                                                         \
    for (int k_ = 0; k_ < NP; ++k_) {                                         \
        A1_[k_] = bp1l; B1_[k_] = bp1h;                                       \
        A2_[k_] = bp2l; B2_[k_] = bp2h;                                       \
    }                                                                         \
    /* block A */                                                             \
    {                                                                         \
        ull v_[NP];                                                           \
        _Pragma("unroll")                                                     \
        for (int j_ = 0; j_ < D_; ++j_) {                                     \
            loadv<NP>(&xsw[rb_][j_][0], v_);                                  \
            gsteps<NP>(wxp0[j_], wxp1[j_], v_, A1_, B1_);                     \
        }                                                                     \
        _Pragma("unroll")                                                     \
        for (int jq_ = 0; jq_ < 4; ++jq_) {                                   \
            float4 w20 = *(const float4*)&wsm[0][r0][4 * jq_];                \
            float4 w21 = *(const float4*)&wsm[0][r1][4 * jq_];                \
            _Pragma("unroll")                                                 \
            for (int jj_ = 0; jj_ < 4; ++jj_) {                               \
                int j_ = 4 * jq_ + jj_;                                       \
                loadv<NP>(&hsw[0][rb_][j_][0], v_);                           \
                gsteps<NP>(whp0[j_], whp1[j_], v_, A1_, B1_);                 \
                float s0 = ((const float*)&w20)[jj_];                         \
                float s1 = ((const float*)&w21)[jj_];                         \
                gsteps<NP>(pack2(s0, s0), pack2(s1, s1), v_, A2_, B2_);       \
            }                                                                 \
        }                                                                     \
    }                                                                         \
    if (U1) do_update<NP>(A1_, B1_, low, c1p0, c1p1,                          \
                          &hsw[0][wb_][unit][0]);                             \
    /* block B */                                                             \
    _Pragma("unroll")                                                         \
    for (int k_ = 0; k_ < NP; ++k_) { A3_[k_] = bp3l; B3_[k_] = bp3h; }       \
    {                                                                         \
        ull v_[NP];                                                           \
        _Pragma("unroll")                                                     \
        for (int jq_ = 0; jq_ < 4; ++jq_) {                                   \
            float4 w2h0 = *(const float4*)&wsm[0][r0][16 + 4 * jq_];          \
            float4 w2h1 = *(const float4*)&wsm[0][r1][16 + 4 * jq_];          \
            float4 w3i0 = *(const float4*)&wsm[1][r0][4 * jq_];               \
            float4 w3i1 = *(const float4*)&wsm[1][r1][4 * jq_];               \
            _Pragma("unroll")                                                 \
            for (int jj_ = 0; jj_ < 4; ++jj_) {                               \
                int j_ = 4 * jq_ + jj_;                                       \
                loadv<NP>(&hsw[1][rb_][j_][0], v_);                           \
                float s0 = ((const float*)&w2h0)[jj_];                        \
                float s1 = ((const float*)&w2h1)[jj_];                        \
                gsteps<NP>(pack2(s0, s0), pack2(s1, s1), v_, A2_, B2_);       \
                float t0 = ((const float*)&w3i0)[jj_];                        \
                float t1 = ((const float*)&w3i1)[jj_];                        \
                gsteps<NP>(pack2(t0, t0), pack2(t1, t1), v_, A3_, B3_);       \
            }                                                                 \
        }                                                                     \
    }                                                                         \
    if (U2) do_update<NP>(A2_, B2_, low, c2p0, c2p1,                          \
                          &hsw[1][wb_][unit][0]);                             \
    /* block C */                                                             \
    {                                                                         \
        ull v_[NP];                                                           \
        _Pragma("unroll")                                                     \
        for (int jq_ = 0; jq_ < 4; ++jq_) {                                   \
            float4 w3h0 = *(const float4*)&wsm[1][r0][16 + 4 * jq_];          \
            float4 w3h1 = *(const float4*)&wsm[1][r1][16 + 4 * jq_];          \
            _Pragma("unroll")                                                 \
            for (int jj_ = 0; jj_ < 4; ++jj_) {                               \
                int j_ = 4 * jq_ + jj_;                                       \
                loadv<NP>(&hsw[2][rb_][j_][0], v_);                           \
                float s0 = ((const float*)&w3h0)[jj_];                        \
                float s1 = ((const float*)&w3h1)[jj_];                        \
                gsteps<NP>(pack2(s0, s0), pack2(s1, s1), v_, A3_, B3_);       \
            }                                                                 \
        }                                                                     \
    }                                                                         \
    if (U3) h3f = do_update<NP>(A3_, B3_, low, c3p0, c3p1,                    \
                                &hsw[2][wb_][unit][0]);                       \
    xsw[wb_][xj][xc] = xn_;                                                   \
    __syncwarp();                                                             \
} while (0)

    ITER(0, true, false, false);
    ITER(1, true, true, false);
#pragma unroll 1
    for (int k = 2; k < T_; ++k) ITER(k, true, true, true);
    ITER(T_, false, true, true);
    ITER(T_ + 1, false, false, true);
#undef ITER

    // final layer-3 h (step T-1), ghost-guarded.
    if (NP == 4) {
        int cb = b0 + (low ? 0 : 4);
        const float hv[4] = {h3f.x, h3f.y, h3f.z, h3f.w};
#pragma unroll
        for (int k = 0; k < 4; ++k)
            if (cb + k < B_) g3[(cb + k) * H_ + unit] = hv[k];
    } else {
        if (low) {
            if (b0 + 0 < B_) g3[(b0 + 0) * H_ + unit] = h3f.x;
            if (b0 + 1 < B_) g3[(b0 + 1) * H_ + unit] = h3f.y;
        } else {
            const float hv[4] = {h3f.x, h3f.y, h3f.z, h3f.w};
#pragma unroll
            for (int k = 0; k < 4; ++k)
                if (b0 + 2 + k < B_) g3[(b0 + 2 + k) * H_ + unit] = hv[k];
        }
    }
}

__global__ void __launch_bounds__(256, 1) lstm_kernel(Params p) {
    __shared__ float wsm[2][64][WPITCH];   // L2/L3 weights [layer][row][ih|hh]
    __shared__ __align__(16) float xs[WPC][2][D_][8];
    __shared__ __align__(16) float hs[WPC][3][2][H_][8];

    const int tid  = threadIdx.x;
    const int lane = tid & 31;
    const int w    = tid >> 5;
    const int dir  = blockIdx.x / CTAS_PER_DIR;
    const int gbase = (blockIdx.x % CTAS_PER_DIR) * CHAINS_PER_CTA;
    const bool np4 = (w < 4);
    const int b0 = gbase + (np4 ? w * 8 : 32 + (w - 4) * 6);
    const bool low = lane < 16;
    const int unit = lane & 15;

    const float* const* ws = &p.w[dir * 12];

    // ---- cooperative fill of L2/L3 weight table ----
    // Sigmoid gate rows (i:0-15, f:16-31, o:48-63) pre-scaled by 0.5;
    // tanh rows (g:32-47) unscaled.
    for (int i = tid; i < 2 * 64 * 32; i += 256) {
        int layer = i >> 11, rem = i & 2047, row = rem >> 5, col = rem & 31;
        float v = (col < 16) ? ws[4 + layer * 4][row * 16 + col]
                             : ws[5 + layer * 4][row * 16 + (col - 16)];
        float sc = (row >= 32 && row < 48) ? 1.0f : 0.5f;
        wsm[layer][row][col] = v * sc;
    }

    // ---- L1 weights pre-packed (duplicated), pre-scaled; per-row biases ----
    const int r0 = lane, r1 = lane + 32;
    const float sc0 = 0.5f;               // r0 rows (i/f): sigmoid
    const float sc1 = low ? 1.0f : 0.5f;  // r1: g (tanh) low, o (sigmoid) high
    ull wxp0[D_], wxp1[D_], whp0[H_], whp1[H_];
#pragma unroll
    for (int j = 0; j < D_; ++j) {
        float a = ws[0][r0 * D_ + j] * sc0, b = ws[0][r1 * D_ + j] * sc1;
        wxp0[j] = pack2(a, a);
        wxp1[j] = pack2(b, b);
    }
#pragma unroll
    for (int j = 0; j < H_; ++j) {
        float a = ws[1][r0 * H_ + j] * sc0, b = ws[1][r1 * H_ + j] * sc1;
        whp0[j] = pack2(a, a);
        whp1[j] = pack2(b, b);
    }
    const float b1l = (ws[2][r0] + ws[3][r0]) * sc0,   b1h = (ws[2][r1] + ws[3][r1]) * sc1;
    const float b2l = (ws[6][r0] + ws[7][r0]) * sc0,   b2h = (ws[6][r1] + ws[7][r1]) * sc1;
    const float b3l = (ws[10][r0] + ws[11][r0]) * sc0, b3h = (ws[10][r1] + ws[11][r1]) * sc1;
    const ull bp1l = pack2(b1l, b1l), bp1h = pack2(b1h, b1h);
    const ull bp2l = pack2(b2l, b2l), bp2h = pack2(b2h, b2h);
    const ull bp3l = pack2(b3l, b3l), bp3h = pack2(b3h, b3h);

    __syncthreads();  // weight table visible

    float* g3 = &g_h3[dir][0][0];
    if (np4)
        run_warp<4>(p.y, xs[w], hs[w], wsm,
                    wxp0, wxp1, whp0, whp1,
                    bp1l, bp1h, bp2l, bp2h, bp3l, bp3h,
                    r0, r1, low, unit, lane, b0, dir, g3);
    else
        run_warp<3>(p.y, xs[w], hs[w], wsm,
                    wxp0, wxp1, whp0, whp1,
                    bp1l, bp1h, bp2l, bp2h, bp3l, bp3h,
                    r0, r1, low, unit, lane, b0, dir, g3);
}

// out[b,k] = b_out[k] + sum_j W_out[k][j]*hf3[b][j] + W_out[k][16+j]*hb3[b][j]
__global__ void proj_kernel(const float* __restrict__ Wo,
                            const float* __restrict__ bo,
                            float* __restrict__ out) {
    int b = blockIdx.x * blockDim.x + threadIdx.x;
    if (b >= B_) return;
    float a0 = bo[0], a1 = bo[1], a2 = bo[2], a3 = bo[3];
#pragma unroll
    for (int j = 0; j < H_; ++j) {
        float hf = g_h3[0][b][j];
        a0 += Wo[0 * 32 + j] * hf;
        a1 += Wo[1 * 32 + j] * hf;
        a2 += Wo[2 * 32 + j] * hf;
        a3 += Wo[3 * 32 + j] * hf;
    }
#pragma unroll
    for (int j = 0; j < H_; ++j) {
        float hb = g_h3[1][b][j];
        a0 += Wo[0 * 32 + 16 + j] * hb;
        a1 += Wo[1 * 32 + 16 + j] * hb;
        a2 += Wo[2 * 32 + 16 + j] * hb;
        a3 += Wo[3 * 32 + 16 + j] * hb;
    }
    ((float4*)out)[b] = make_float4(a0, a1, a2, a3);
}

extern "C" void kernel_launch(void* const* d_in, const int* in_sizes, int n_in,
                              void* d_out, int out_size) {
    (void)in_sizes; (void)n_in; (void)out_size;
    Params p;
    p.y = (const float*)d_in[0];
    for (int i = 0; i < 24; ++i) p.w[i] = (const float*)d_in[1 + i];

    lstm_kernel<<<NCTA, 256>>>(p);
    proj_kernel<<<(B_ + 127) / 128, 128>>>((const float*)d_in[25],
                                           (const float*)d_in[26],
                                           (float*)d_out);
}